// round 12
// baseline (speedup 1.0000x reference)
#include <cuda_runtime.h>
#include <cuda_bf16.h>
#include <cuda_fp16.h>

#define H     128
#define BATCH 8
#define TQ    512
#define TK    512

// Device scratch (allocation-free rule: __device__ globals)
__device__ __align__(16) __half2 g_kph[BATCH * (H/2) * TK];  // [b][h/2][k] packed h-pairs
__device__ __align__(16) float   g_WaT[H * H];               // Wa transposed: WaT[k][h]

__device__ __forceinline__ __half2 tanh2(__half2 x) {
    unsigned xi = *(unsigned*)&x, yi;
    asm("tanh.approx.f16x2 %0, %1;" : "=r"(yi) : "r"(xi));
    return *(__half2*)&yi;
}

// ---------------------------------------------------------------------------
// Kernel 1: prep, 256 threads/block for latency hiding.
//   z==0: k-projection  g_kph[b][h/2][t] = keys @ Ua_w^T + Ua_b  (half2 pairs)
//         thread = (h, row-half): 8 accumulators, W row shared by 2 threads (L1)
//   z==1: transpose Wa into g_WaT (only b==0 blocks active)
// grid = (32, B, 2), block = 256
// ---------------------------------------------------------------------------
__global__ void __launch_bounds__(256) prep_kernel(
    const float* __restrict__ keys,
    const float* __restrict__ Ua_w, const float* __restrict__ Ua_b,
    const float* __restrict__ Wa_w)
{
    const int tile = blockIdx.x;   // 32 tiles of 16 rows
    const int b    = blockIdx.y;

    if (blockIdx.z == 1) {
        if (b != 0) return;
        const int r0 = tile * 4;
        #pragma unroll
        for (int i = threadIdx.x; i < 4 * H; i += 256) {
            int r = i >> 7, c = i & 127;
            g_WaT[(size_t)c * H + r0 + r] = Wa_w[(size_t)(r0 + r) * H + c];
        }
        return;
    }

    const int t0 = tile * 16;
    __shared__ __align__(16) float xs[16][H];   // 8 KB
    __shared__ float sh[H][16];                 // 8 KB (h-pair packing)

    const float4* xsrc = (const float4*)(keys + (size_t)(b * 512 + t0) * H);
    #pragma unroll
    for (int i = threadIdx.x; i < 16 * H / 4; i += 256)
        ((float4*)xs)[i] = xsrc[i];
    __syncthreads();

    const int h  = threadIdx.x & 127;  // output column
    const int rh = threadIdx.x >> 7;   // row half: rows rh*8 .. rh*8+7

    float acc[8];
    const float bv = Ua_b[h];
    #pragma unroll
    for (int t = 0; t < 8; t++) acc[t] = bv;

    const float4* Wrow = (const float4*)(Ua_w + h * H);
    #pragma unroll 4
    for (int i = 0; i < H / 4; i++) {
        float4 w4 = Wrow[i];               // 2 threads/row -> 2nd is L1 hit
        #pragma unroll
        for (int t = 0; t < 8; t++) {
            float4 xv = ((const float4*)xs[rh * 8 + t])[i];
            acc[t] = fmaf(xv.x, w4.x, fmaf(xv.y, w4.y, fmaf(xv.z, w4.z, fmaf(xv.w, w4.w, acc[t]))));
        }
    }

    #pragma unroll
    for (int t = 0; t < 8; t++) sh[h][rh * 8 + t] = acc[t];
    __syncthreads();

    __half2* dst = g_kph + (size_t)b * (H/2) * TK + t0;
    #pragma unroll
    for (int r = 0; r < 4; r++) {
        int idx = threadIdx.x + 256 * r;   // 0..1023
        int t   = idx & 15;
        int j   = idx >> 4;                // h-pair 0..63
        dst[(size_t)j * TK + t] = __floats2half2_rn(sh[2*j][t], sh[2*j+1][t]);
    }
}

// ---------------------------------------------------------------------------
// Kernel 2: FUSED q-projection + scores + softmax (round-11, kept — fusion
// verified free). grid (TQ/4, B), block 128 (4 warps, 1 q/warp).
// Hot loop: HADD2 -> tanh.f16x2 (MUFU floor) -> HFMA2; f32 flush every 8.
// ---------------------------------------------------------------------------
__global__ void __launch_bounds__(128) score_kernel(
    const float* __restrict__ queries,
    const float* __restrict__ Wa_b,
    const float* __restrict__ Va_w,
    float* __restrict__ w_out)     // (B, TQ, TK)
{
    __shared__ __align__(16) float  qs[4][H];    // 2 KB raw query rows
    __shared__ __align__(8)  float2 qm[4][H/2];  // per warp: {q2 bits, va2 bits}

    const int b    = blockIdx.y;
    const int wid  = threadIdx.x >> 5;
    const int lane = threadIdx.x & 31;
    const int q    = blockIdx.x * 4 + wid;

    ((float4*)qs)[threadIdx.x] =
        ((const float4*)(queries + (size_t)(b * TQ + blockIdx.x * 4) * H))[threadIdx.x];
    __syncthreads();

    // ---- Fused q-projection: qp[4lane..4lane+3] = q-row @ Wa^T + b ----
    float4 acc = ((const float4*)Wa_b)[lane];
    {
        const float*  qrow = qs[wid];
        const float4* WT   = (const float4*)g_WaT + lane;   // WaT[k][4lane..+3]
        #pragma unroll 8
        for (int k = 0; k < H; k++) {
            float  xk = qrow[k];        // broadcast LDS
            float4 wv = WT[k * 32];     // coalesced LDG.128, L1-hot
            acc.x = fmaf(xk, wv.x, acc.x);
            acc.y = fmaf(xk, wv.y, acc.y);
            acc.z = fmaf(xk, wv.z, acc.z);
            acc.w = fmaf(xk, wv.w, acc.w);
        }
    }
    {
        __half2 q2a = __floats2half2_rn(acc.x, acc.y);
        __half2 q2b = __floats2half2_rn(acc.z, acc.w);
        float4  vv  = ((const float4*)Va_w)[lane];
        __half2 va0 = __floats2half2_rn(vv.x, vv.y);
        __half2 va1 = __floats2half2_rn(vv.z, vv.w);
        qm[wid][2*lane]   = make_float2(__uint_as_float(*(unsigned*)&q2a),
                                        __uint_as_float(*(unsigned*)&va0));
        qm[wid][2*lane+1] = make_float2(__uint_as_float(*(unsigned*)&q2b),
                                        __uint_as_float(*(unsigned*)&va1));
    }
    __syncwarp();

    // ---- Hot loop: scores over 512 keys (lane owns keys 64t + 2lane + e) ----
    float a[16];
    #pragma unroll
    for (int i = 0; i < 16; i++) a[i] = 0.f;

    const uint2* kb = (const uint2*)(g_kph + (size_t)b * (H/2) * TK) + lane;

    #pragma unroll 1
    for (int jb = 0; jb < 8; jb++) {           // 8 blocks of 8 h-pairs
        __half2 acc2[16];
        #pragma unroll
        for (int i = 0; i < 16; i++) acc2[i] = __half2half2(__float2half(0.f));

        #pragma unroll
        for (int j2 = 0; j2 < 8; j2++) {
            int j = jb * 8 + j2;
            float2 meta = qm[wid][j];          // broadcast LDS.64
            unsigned qb2 = __float_as_uint(meta.x);
            unsigned vb2 = __float_as_uint(meta.y);
            __half2 q2  = *(__half2*)&qb2;
            __half2 va2 = *(__half2*)&vb2;

            const uint2* kr = kb + j * (TK / 2);
            uint2 kk[8];
            #pragma unroll
            for (int t = 0; t < 8; t++) kk[t] = kr[t * 32];   // MLP=8 LDG.64
            #pragma unroll
            for (int t = 0; t < 8; t++) {
                __half2 k0 = *(__half2*)&kk[t].x;
                __half2 k1 = *(__half2*)&kk[t].y;
                acc2[2*t]   = __hfma2(va2, tanh2(__hadd2(q2, k0)), acc2[2*t]);
                acc2[2*t+1] = __hfma2(va2, tanh2(__hadd2(q2, k1)), acc2[2*t+1]);
            }
        }
        #pragma unroll
        for (int i = 0; i < 16; i++) {
            float2 f = __half22float2(acc2[i]);
            a[i] += f.x + f.y;                 // fold even/odd-h partial sums
        }
    }

    // ---- softmax in registers ----
    float m = a[0];
    #pragma unroll
    for (int i = 1; i < 16; i++) m = fmaxf(m, a[i]);
    #pragma unroll
    for (int o = 16; o > 0; o >>= 1)
        m = fmaxf(m, __shfl_xor_sync(0xffffffffu, m, o));

    float s = 0.f;
    #pragma unroll
    for (int i = 0; i < 16; i++) { a[i] = __expf(a[i] - m); s += a[i]; }
    #pragma unroll
    for (int o = 16; o > 0; o >>= 1)
        s += __shfl_xor_sync(0xffffffffu, s, o);

    const float inv = __fdividef(1.f, s);
    float* wrow = w_out + (size_t)(b * TQ + q) * TK;
    #pragma unroll
    for (int t = 0; t < 8; t++)
        *(float2*)(wrow + 64 * t + 2 * lane) =
            make_float2(a[2*t] * inv, a[2*t+1] * inv);
}

// ---------------------------------------------------------------------------
// Kernel 3: context = w @ keys (round-6 per-warp streaming — best measured).
// grid (TQ/8, B), block 128 (4 warps). Two queries per warp.
// ---------------------------------------------------------------------------
__global__ void __launch_bounds__(128) ctx_kernel(
    const float* __restrict__ keys,
    const float* __restrict__ w_in,    // (B, TQ, TK)
    float* __restrict__ ctx_out)       // (B, TQ, H)
{
    __shared__ float wsm[8][TK];

    const int b    = blockIdx.y;
    const int wid  = threadIdx.x >> 5;
    const int lane = threadIdx.x & 31;
    const int q0   = blockIdx.x * 8 + 2 * wid;

    {
        const float4* src = (const float4*)(w_in + (size_t)(b * TQ + q0) * TK);
        float4* dst = (float4*)&wsm[2 * wid][0];
        #pragma unroll
        for (int i = 0; i < 8; i++)
            dst[lane + 32 * i] = src[lane + 32 * i];
    }
    __syncwarp();

    float4 acc0 = make_float4(0.f, 0.f, 0.f, 0.f);
    float4 acc1 = make_float4(0.f, 0.f, 0.f, 0.f);
    const float4* kb = (const float4*)(keys + (size_t)b * TK * H) + lane;
    const float* w0 = wsm[2 * wid];
    const float* w1 = wsm[2 * wid + 1];
    #pragma unroll 8
    for (int key = 0; key < TK; key++) {
        float4 kv = kb[key * (H / 4)];           // coalesced LDG.128, L1/L2-hot
        float wa = w0[key];                      // broadcast LDS
        float wb = w1[key];
        acc0.x = fmaf(wa, kv.x, acc0.x); acc0.y = fmaf(wa, kv.y, acc0.y);
        acc0.z = fmaf(wa, kv.z, acc0.z); acc0.w = fmaf(wa, kv.w, acc0.w);
        acc1.x = fmaf(wb, kv.x, acc1.x); acc1.y = fmaf(wb, kv.y, acc1.y);
        acc1.z = fmaf(wb, kv.z, acc1.z); acc1.w = fmaf(wb, kv.w, acc1.w);
    }
    float4* crow = (float4*)(ctx_out + (size_t)(b * TQ + q0) * H);
    crow[lane]           = acc0;
    crow[lane + (H / 4)] = acc1;
}

// ---------------------------------------------------------------------------
extern "C" void kernel_launch(void* const* d_in, const int* in_sizes, int n_in,
                              void* d_out, int out_size)
{
    const float* queries = (const float*)d_in[0];
    const float* keys    = (const float*)d_in[1];
    const float* Wa_w    = (const float*)d_in[2];
    const float* Wa_b    = (const float*)d_in[3];
    const float* Ua_w    = (const float*)d_in[4];
    const float* Ua_b    = (const float*)d_in[5];
    const float* Va_w    = (const float*)d_in[6];
    // Va bias (d_in[7]) cancels in softmax -> unused.

    float* ctx_out = (float*)d_out;                     // (B, TQ, H)
    float* w_out   = ctx_out + BATCH * TQ * H;          // (B, TQ, TK)

    dim3 g1(32, BATCH, 2);
    prep_kernel<<<g1, 256>>>(keys, Ua_w, Ua_b, Wa_w);

    dim3 g2(TQ / 4, BATCH);
    score_kernel<<<g2, 128>>>(queries, Wa_b, Va_w, w_out);

    dim3 g3(TQ / 8, BATCH);
    ctx_kernel<<<g3, 128>>>(keys, w_out, ctx_out);
}

// round 13
// speedup vs baseline: 1.1500x; 1.1500x over previous
#include <cuda_runtime.h>
#include <cuda_bf16.h>
#include <cuda_fp16.h>

#define H     128
#define BATCH 8
#define TQ    512
#define TK    512

// Device scratch (allocation-free rule: __device__ globals)
__device__ __align__(16) __half2 g_kph[BATCH * (H/2) * TK];  // [b][h/2][k] packed h-pairs
__device__ __align__(16) float   g_WaT[H * H];               // Wa transposed: WaT[k][h]

__device__ __forceinline__ __half2 tanh2(__half2 x) {
    unsigned xi = *(unsigned*)&x, yi;
    asm("tanh.approx.f16x2 %0, %1;" : "=r"(yi) : "r"(xi));
    return *(__half2*)&yi;
}

// ---------------------------------------------------------------------------
// Kernel 1: prep (round-11 128-thread / 16-accumulator form — best measured).
//   z==0: k-projection  g_kph[b][h/2][t] = keys @ Ua_w^T + Ua_b  (half2 pairs)
//   z==1: transpose Wa into g_WaT (only b==0 blocks active)
// grid = (32, B, 2), block = 128
// ---------------------------------------------------------------------------
__global__ void __launch_bounds__(128) prep_kernel(
    const float* __restrict__ keys,
    const float* __restrict__ Ua_w, const float* __restrict__ Ua_b,
    const float* __restrict__ Wa_w)
{
    const int tile = blockIdx.x;   // 32 tiles of 16 rows
    const int b    = blockIdx.y;

    if (blockIdx.z == 1) {
        if (b != 0) return;
        const int r0 = tile * 4;
        #pragma unroll
        for (int i = threadIdx.x; i < 4 * H; i += 128) {
            int r = i >> 7, c = i & 127;
            g_WaT[(size_t)c * H + r0 + r] = Wa_w[(size_t)(r0 + r) * H + c];
        }
        return;
    }

    const int t0 = tile * 16;
    __shared__ __align__(16) float xs[16][H];
    __shared__ float sh[H][16];    // for h-pair packing

    const float4* xsrc = (const float4*)(keys + (size_t)(b * 512 + t0) * H);
    #pragma unroll
    for (int i = threadIdx.x; i < 16 * H / 4; i += 128)
        ((float4*)xs)[i] = xsrc[i];
    __syncthreads();

    const int h = threadIdx.x;
    float acc[16];
    const float bv = Ua_b[h];
    #pragma unroll
    for (int t = 0; t < 16; t++) acc[t] = bv;

    const float4* Wrow = (const float4*)(Ua_w + h * H);
    #pragma unroll 4
    for (int i = 0; i < H / 4; i++) {
        float4 w4 = Wrow[i];
        #pragma unroll
        for (int t = 0; t < 16; t++) {
            float4 xv = ((const float4*)xs[t])[i];
            acc[t] = fmaf(xv.x, w4.x, fmaf(xv.y, w4.y, fmaf(xv.z, w4.z, fmaf(xv.w, w4.w, acc[t]))));
        }
    }

    #pragma unroll
    for (int t = 0; t < 16; t++) sh[h][t] = acc[t];
    __syncthreads();
    __half2* dst = g_kph + (size_t)b * (H/2) * TK + t0;
    #pragma unroll
    for (int r = 0; r < 8; r++) {
        int idx = threadIdx.x + 128 * r;   // 0..1023
        int t   = idx & 15;
        int j   = idx >> 4;                // h-pair 0..63
        dst[(size_t)j * TK + t] = __floats2half2_rn(sh[2*j][t], sh[2*j+1][t]);
    }
}

// ---------------------------------------------------------------------------
// Kernel 2: FULLY FUSED q-projection + scores + softmax + context.
// grid (TQ/4, B), block 128 (4 warps, 1 q/warp).
// Context loop (FFMA + coalesced L2-hot loads) hides under the MUFU-bound
// score loop of co-resident warps; w round-trip through global eliminated.
// ---------------------------------------------------------------------------
__global__ void __launch_bounds__(128) score_kernel(
    const float* __restrict__ queries,
    const float* __restrict__ keys,
    const float* __restrict__ Wa_b,
    const float* __restrict__ Va_w,
    float* __restrict__ ctx_out,   // (B, TQ, H)
    float* __restrict__ w_out)     // (B, TQ, TK)
{
    __shared__ __align__(16) float  qs[4][H];    // 2 KB raw query rows
    __shared__ __align__(8)  float2 qm[4][H/2];  // 4 KB {q2 bits, va2 bits}
    __shared__ float wsm[4][TK];                 // 8 KB softmax weights

    const int b    = blockIdx.y;
    const int wid  = threadIdx.x >> 5;
    const int lane = threadIdx.x & 31;
    const int q    = blockIdx.x * 4 + wid;

    ((float4*)qs)[threadIdx.x] =
        ((const float4*)(queries + (size_t)(b * TQ + blockIdx.x * 4) * H))[threadIdx.x];
    __syncthreads();

    // ---- Fused q-projection: qp[4lane..4lane+3] = q-row @ Wa^T + b ----
    float4 acc = ((const float4*)Wa_b)[lane];
    {
        const float*  qrow = qs[wid];
        const float4* WT   = (const float4*)g_WaT + lane;   // WaT[k][4lane..+3]
        #pragma unroll 8
        for (int k = 0; k < H; k++) {
            float  xk = qrow[k];        // broadcast LDS
            float4 wv = WT[k * 32];     // coalesced LDG.128, L1-hot
            acc.x = fmaf(xk, wv.x, acc.x);
            acc.y = fmaf(xk, wv.y, acc.y);
            acc.z = fmaf(xk, wv.z, acc.z);
            acc.w = fmaf(xk, wv.w, acc.w);
        }
    }
    {
        __half2 q2a = __floats2half2_rn(acc.x, acc.y);
        __half2 q2b = __floats2half2_rn(acc.z, acc.w);
        float4  vv  = ((const float4*)Va_w)[lane];
        __half2 va0 = __floats2half2_rn(vv.x, vv.y);
        __half2 va1 = __floats2half2_rn(vv.z, vv.w);
        qm[wid][2*lane]   = make_float2(__uint_as_float(*(unsigned*)&q2a),
                                        __uint_as_float(*(unsigned*)&va0));
        qm[wid][2*lane+1] = make_float2(__uint_as_float(*(unsigned*)&q2b),
                                        __uint_as_float(*(unsigned*)&va1));
    }
    __syncwarp();

    // ---- Score hot loop (MUFU floor): lane owns keys 64t + 2lane + e ----
    float a[16];
    #pragma unroll
    for (int i = 0; i < 16; i++) a[i] = 0.f;

    const uint2* kb2 = (const uint2*)(g_kph + (size_t)b * (H/2) * TK) + lane;

    #pragma unroll 1
    for (int jb = 0; jb < 8; jb++) {           // 8 blocks of 8 h-pairs
        __half2 acc2[16];
        #pragma unroll
        for (int i = 0; i < 16; i++) acc2[i] = __half2half2(__float2half(0.f));

        #pragma unroll
        for (int j2 = 0; j2 < 8; j2++) {
            int j = jb * 8 + j2;
            float2 meta = qm[wid][j];          // broadcast LDS.64
            unsigned qb2b = __float_as_uint(meta.x);
            unsigned vb2b = __float_as_uint(meta.y);
            __half2 q2  = *(__half2*)&qb2b;
            __half2 va2 = *(__half2*)&vb2b;

            const uint2* kr = kb2 + j * (TK / 2);
            uint2 kk[8];
            #pragma unroll
            for (int t = 0; t < 8; t++) kk[t] = kr[t * 32];   // MLP=8 LDG.64
            #pragma unroll
            for (int t = 0; t < 8; t++) {
                __half2 k0 = *(__half2*)&kk[t].x;
                __half2 k1 = *(__half2*)&kk[t].y;
                acc2[2*t]   = __hfma2(va2, tanh2(__hadd2(q2, k0)), acc2[2*t]);
                acc2[2*t+1] = __hfma2(va2, tanh2(__hadd2(q2, k1)), acc2[2*t+1]);
            }
        }
        #pragma unroll
        for (int i = 0; i < 16; i++) {
            float2 f = __half22float2(acc2[i]);
            a[i] += f.x + f.y;                 // fold even/odd-h partial sums
        }
    }

    // ---- softmax in registers ----
    float m = a[0];
    #pragma unroll
    for (int i = 1; i < 16; i++) m = fmaxf(m, a[i]);
    #pragma unroll
    for (int o = 16; o > 0; o >>= 1)
        m = fmaxf(m, __shfl_xor_sync(0xffffffffu, m, o));

    float s = 0.f;
    #pragma unroll
    for (int i = 0; i < 16; i++) { a[i] = __expf(a[i] - m); s += a[i]; }
    #pragma unroll
    for (int o = 16; o > 0; o >>= 1)
        s += __shfl_xor_sync(0xffffffffu, s, o);

    const float inv = __fdividef(1.f, s);
    float* wrow = w_out + (size_t)(b * TQ + q) * TK;
    #pragma unroll
    for (int t = 0; t < 8; t++) {
        float2 wp = make_float2(a[2*t] * inv, a[2*t+1] * inv);
        int off = 64 * t + 2 * lane;
        *(float2*)(wrow + off)      = wp;      // required output (coalesced STG.64)
        *(float2*)(&wsm[wid][off])  = wp;      // for fused ctx broadcast reads
    }
    __syncwarp();

    // ---- Fused context: ctx[q][h] = sum_k w[k] * keys[k][h] ----
    float4 cacc = make_float4(0.f, 0.f, 0.f, 0.f);
    const float4* kb = (const float4*)(keys + (size_t)b * TK * H) + lane;
    const float* w0 = wsm[wid];
    #pragma unroll 8
    for (int key = 0; key < TK; key++) {
        float4 kv = kb[key * (H / 4)];         // coalesced LDG.128, L2-hot
        float  wa = w0[key];                   // broadcast LDS
        cacc.x = fmaf(wa, kv.x, cacc.x);
        cacc.y = fmaf(wa, kv.y, cacc.y);
        cacc.z = fmaf(wa, kv.z, cacc.z);
        cacc.w = fmaf(wa, kv.w, cacc.w);
    }
    ((float4*)(ctx_out + (size_t)(b * TQ + q) * H))[lane] = cacc;
}

// ---------------------------------------------------------------------------
extern "C" void kernel_launch(void* const* d_in, const int* in_sizes, int n_in,
                              void* d_out, int out_size)
{
    const float* queries = (const float*)d_in[0];
    const float* keys    = (const float*)d_in[1];
    const float* Wa_w    = (const float*)d_in[2];
    const float* Wa_b    = (const float*)d_in[3];
    const float* Ua_w    = (const float*)d_in[4];
    const float* Ua_b    = (const float*)d_in[5];
    const float* Va_w    = (const float*)d_in[6];
    // Va bias (d_in[7]) cancels in softmax -> unused.

    float* ctx_out = (float*)d_out;                     // (B, TQ, H)
    float* w_out   = ctx_out + BATCH * TQ * H;          // (B, TQ, TK)

    dim3 g1(32, BATCH, 2);
    prep_kernel<<<g1, 128>>>(keys, Ua_w, Ua_b, Wa_w);

    dim3 g2(TQ / 4, BATCH);
    score_kernel<<<g2, 128>>>(queries, keys, Wa_b, Va_w, ctx_out, w_out);
}